// round 13
// baseline (speedup 1.0000x reference)
#include <cuda_runtime.h>

#define DB 160
#define HB 160
#define WB 160
#define NB 2
#define NTOT (NB*DB*HB*WB)              // 8,192,000
#define PW (WB/32)                       // 5 packed words per row
#define NWORDS (NTOT/32)                 // 256,000 words
#define TPB 256
#define PACK_EPT 4
#define PACK_BLOCKS (NTOT/(TPB*PACK_EPT))// 8000
#define EPT 16                           // elements per thread (half word)
#define GRID (NTOT/(TPB*EPT))            // 2000

// acc[0]=sum (1+w)*bce, acc[1]=sum p, acc[2]=sum p*t, acc[3]=sum t
__device__ double g_acc[4];
__device__ unsigned g_count;
__device__ unsigned g_packed[NWORDS];

// ---------------- pack via warp ballot -----------------------------------
__global__ __launch_bounds__(TPB) void pack_kernel(const int* __restrict__ target) {
    if (blockIdx.x == 0 && threadIdx.x < 4) g_acc[threadIdx.x] = 0.0;
    const int tid  = blockIdx.x * TPB + threadIdx.x;
    const int lane = threadIdx.x & 31;
    const int gw   = tid >> 5;
    const int ebase = gw * 32 * PACK_EPT;
    unsigned keep = 0u;
    #pragma unroll
    for (int i = 0; i < PACK_EPT; i++) {
        const int v = target[ebase + i * 32 + lane];
        const unsigned w = __ballot_sync(0xffffffffu, v != 0);
        if (lane == i) keep = w;
    }
    if (lane < PACK_EPT) g_packed[gw * PACK_EPT + lane] = keep;
}

// XOR swizzle: conflict-free for writes (k*32+lane) and reads (lane*4+q).
__device__ __forceinline__ int swz(int j) { return j ^ ((j >> 3) & 7); }

// ---------------- main: fused loss, 16 elts/thread ------------------------
__global__ __launch_bounds__(TPB, 7) void loss_main_kernel(
    const float* __restrict__ logits,
    const float* __restrict__ area_table,
    float* __restrict__ out)
{
    __shared__ float4 s_tile[TPB * 4];     // 16 KB: per-warp 2 KB logits tiles
    __shared__ float s_area2[256];
    __shared__ float s_red[4][TPB / 32];

    // Bit-reversed (1 + area) table; code==0 -> multiplier 1 (boundary free).
    s_area2[threadIdx.x] = 1.f + area_table[__brev((unsigned)threadIdx.x) >> 24];
    __syncthreads();

    const int lane = threadIdx.x & 31;
    const int warp = threadIdx.x >> 5;
    const int hw   = blockIdx.x * TPB + threadIdx.x;   // half-word id
    const int t    = hw >> 1;                           // word id
    const int half = hw & 1;
    const int eoff = half << 4;                         // 0 or 16

    // ---- COALESCED logits load -> swizzled per-warp smem tile (2 KB) ----
    {
        const float4* __restrict__ lg4 = (const float4*)logits;
        const int gbase = blockIdx.x * (TPB * 4) + warp * 128;   // float4 units
        float4 v[4];
        #pragma unroll
        for (int k = 0; k < 4; k++) v[k] = lg4[gbase + k * 32 + lane];
        #pragma unroll
        for (int k = 0; k < 4; k++) s_tile[warp * 128 + swz(k * 32 + lane)] = v[k];
    }

    const int wi = t % PW;
    int r        = t / PW;
    const int h  = r % HB;
    r            = r / HB;
    const int d  = r % DB;
    const bool interior = (d < DB - 1) && (h < HB - 1);
    const bool hiok     = (wi < PW - 1);
    const bool needhi   = (half == 1) && hiok;   // only e=31 touches next word

    const unsigned m00lo = g_packed[t];
    const unsigned m00hi = needhi ? g_packed[t + 1] : 0u;
    const unsigned cmlo = interior ? m00lo : 0u;
    const unsigned cmhi = interior ? m00hi : 0u;
    unsigned a01lo = 0u, a01hi = 0u, a10lo = 0u, a10hi = 0u, a11lo = 0u, a11hi = 0u;
    if (interior) {
        const unsigned b01lo = g_packed[t + PW];
        const unsigned b10lo = g_packed[t + HB * PW];
        const unsigned b11lo = g_packed[t + HB * PW + PW];
        unsigned b01hi = 0u, b10hi = 0u, b11hi = 0u;
        if (needhi) {
            b01hi = g_packed[t + PW + 1];
            b10hi = g_packed[t + HB * PW + 1];
            b11hi = g_packed[t + HB * PW + PW + 1];
        }
        a01lo = b01lo << 2; a01hi = (b01hi << 2) | (b01lo >> 30);
        a10lo = b10lo << 4; a10hi = (b10hi << 4) | (b10lo >> 28);
        a11lo = b11lo << 6; a11hi = (b11hi << 6) | (b11lo >> 26);
    }

    __syncwarp();   // tile is warp-private

    float acc_wbce = 0.f, acc_p = 0.f, acc_pt = 0.f;
    const float acc_t = (float)__popc((m00lo >> eoff) & 0xFFFFu);

    #pragma unroll
    for (int q = 0; q < 4; q++) {
        const float4 xq = s_tile[warp * 128 + swz(lane * 4 + q)];
        const float xs[4] = {xq.x, xq.y, xq.z, xq.w};
        #pragma unroll
        for (int i2 = 0; i2 < 4; i2++) {
            const int e = eoff + q * 4 + i2;     // runtime base + const offset
            const float xv = xs[i2];
            const bool bit = ((m00lo >> e) & 1u) != 0u;

            // z = e^{-x}; s = 1+z; p = 1/s; bce = x*(1-t) + ln(s)
            const float z = exp2f(-1.442695041f * xv);
            const float s = 1.f + z;
            float p;
            asm("rcp.approx.f32 %0, %1;" : "=f"(p) : "f"(s));
            const float l2s = __log2f(s);
            const float xnt = bit ? 0.f : xv;
            const float bce = fmaf(0.693147181f, l2s, xnt);

            const unsigned code = (__funnelshift_r(cmlo,  cmhi,  e) & 3u)
                                | (__funnelshift_r(a01lo, a01hi, e) & 12u)
                                | (__funnelshift_r(a10lo, a10hi, e) & 48u)
                                | (__funnelshift_r(a11lo, a11hi, e) & 192u);
            float wa1 = s_area2[code];                  // = 1 + weight
            if (q == 3 && i2 == 3 && half == 1 && !hiok) wa1 = 1.f; // w==159

            acc_wbce = fmaf(wa1, bce, acc_wbce);
            acc_p += p;
            if (bit) acc_pt += p;
        }
    }

    // ---- block reduction ----
    float v0 = acc_wbce, v1 = acc_p, v2 = acc_pt, v3 = acc_t;
    #pragma unroll
    for (int off = 16; off > 0; off >>= 1) {
        v0 += __shfl_xor_sync(0xffffffffu, v0, off);
        v1 += __shfl_xor_sync(0xffffffffu, v1, off);
        v2 += __shfl_xor_sync(0xffffffffu, v2, off);
        v3 += __shfl_xor_sync(0xffffffffu, v3, off);
    }
    if (lane == 0) { s_red[0][warp] = v0; s_red[1][warp] = v1; s_red[2][warp] = v2; s_red[3][warp] = v3; }
    __syncthreads();
    if (warp == 0) {
        const int nw = TPB / 32;
        v0 = (lane < nw) ? s_red[0][lane] : 0.f;
        v1 = (lane < nw) ? s_red[1][lane] : 0.f;
        v2 = (lane < nw) ? s_red[2][lane] : 0.f;
        v3 = (lane < nw) ? s_red[3][lane] : 0.f;
        #pragma unroll
        for (int off = 4; off > 0; off >>= 1) {
            v0 += __shfl_xor_sync(0xffffffffu, v0, off);
            v1 += __shfl_xor_sync(0xffffffffu, v1, off);
            v2 += __shfl_xor_sync(0xffffffffu, v2, off);
            v3 += __shfl_xor_sync(0xffffffffu, v3, off);
        }
        if (lane == 0) {
            atomicAdd(&g_acc[0], (double)v0);
            atomicAdd(&g_acc[1], (double)v1);
            atomicAdd(&g_acc[2], (double)v2);
            atomicAdd(&g_acc[3], (double)v3);
            __threadfence();
            const unsigned old = atomicAdd(&g_count, 1u);
            if (old == GRID - 1) {
                const double a0 = atomicAdd(&g_acc[0], 0.0);
                const double a1 = atomicAdd(&g_acc[1], 0.0);
                const double a2 = atomicAdd(&g_acc[2], 0.0);
                const double a3 = atomicAdd(&g_acc[3], 0.0);
                const double wbce = a0 / (double)NTOT;
                const double dice = 1.0 - (2.0 * a2 + 1.0) / (a1 + a3 + 1.0);
                out[0] = (float)(wbce + dice);
                g_count = 0u;    // g_acc re-zeroed by next pack launch
                __threadfence();
            }
        }
    }
}

extern "C" void kernel_launch(void* const* d_in, const int* in_sizes, int n_in,
                              void* d_out, int out_size) {
    const float* logits     = (const float*)d_in[0];
    const int*   target     = (const int*)d_in[1];
    const float* area_table = (const float*)d_in[2];
    float* out = (float*)d_out;

    pack_kernel<<<PACK_BLOCKS, TPB>>>(target);
    loss_main_kernel<<<GRID, TPB>>>(logits, area_table, out);
}

// round 14
// speedup vs baseline: 1.2092x; 1.2092x over previous
#include <cuda_runtime.h>

#define DB 160
#define HB 160
#define WB 160
#define NB 2
#define NTOT (NB*DB*HB*WB)              // 8,192,000
#define PW (WB/32)                       // 5 packed words per row
#define NWORDS (NTOT/32)                 // 256,000 words
#define TPB 256
#define PACK_EPT 4
#define PACK_BLOCKS (NTOT/(TPB*PACK_EPT))// 8000
#define MAIN_BLOCKS (NWORDS/TPB)         // 1000

// acc[0]=sum (1+w)*bce, acc[1]=sum p, acc[2]=sum p*t, acc[3]=sum t
__device__ double g_acc[4];
__device__ unsigned g_count;
__device__ unsigned g_packed[NWORDS + 1024];   // padded: neighbour loads unconditional

// ---------------- pack via warp ballot -----------------------------------
__global__ __launch_bounds__(TPB) void pack_kernel(const int* __restrict__ target) {
    if (blockIdx.x == 0 && threadIdx.x < 4) g_acc[threadIdx.x] = 0.0;
    const int tid  = blockIdx.x * TPB + threadIdx.x;
    const int lane = threadIdx.x & 31;
    const int gw   = tid >> 5;
    const int ebase = gw * 32 * PACK_EPT;
    unsigned keep = 0u;
    #pragma unroll
    for (int i = 0; i < PACK_EPT; i++) {
        const int v = target[ebase + i * 32 + lane];
        const unsigned w = __ballot_sync(0xffffffffu, v != 0);
        if (lane == i) keep = w;
    }
    if (lane < PACK_EPT) g_packed[gw * PACK_EPT + lane] = keep;
}

// XOR swizzle on float4 index within a warp's 256-float4 tile.
__device__ __forceinline__ int swz(int j) { return j ^ ((j >> 3) & 7); }

// ---------------- main: fused loss, 32 elts/thread ------------------------
__global__ __launch_bounds__(TPB) void loss_main_kernel(
    const float* __restrict__ logits,
    const float* __restrict__ area_table,
    float* __restrict__ out)
{
    __shared__ float4 s_tile[TPB * 8];     // 32 KB: per-warp 4 KB logits tiles
    __shared__ float s_area2[256];
    __shared__ float s_red[4][TPB / 32];

    // Bit-reversed (1 + area) table; code==0 -> multiplier 1 (boundary free).
    s_area2[threadIdx.x] = 1.f + area_table[__brev((unsigned)threadIdx.x) >> 24];
    __syncthreads();

    const int lane = threadIdx.x & 31;
    const int warp = threadIdx.x >> 5;
    const int t  = blockIdx.x * TPB + threadIdx.x;            // word id
    const int wi = t % PW;
    int r        = t / PW;
    const int h  = r % HB;
    r            = r / HB;
    const int d  = r % DB;

    const bool interior = (d < DB - 1) && (h < HB - 1);
    const bool hiok     = (wi < PW - 1);

    // ---- COALESCED logits load -> swizzled per-warp smem tile ----
    {
        const float4* __restrict__ lg4 = (const float4*)logits;
        const int gbase = blockIdx.x * (TPB * 8) + warp * 256;   // float4 units
        float4 v[4];
        #pragma unroll
        for (int k = 0; k < 4; k++) v[k] = lg4[gbase + k * 32 + lane];
        #pragma unroll
        for (int k = 0; k < 4; k++) s_tile[warp * 256 + swz(k * 32 + lane)] = v[k];
        #pragma unroll
        for (int k = 4; k < 8; k++) v[k - 4] = lg4[gbase + k * 32 + lane];
        #pragma unroll
        for (int k = 4; k < 8; k++) s_tile[warp * 256 + swz(k * 32 + lane)] = v[k - 4];
    }

    // ---- masks: 8 unconditional loads (padded array), then zero-select ----
    const unsigned m00lo = g_packed[t];
    const unsigned nxt   = g_packed[t + 1];
    const unsigned b01lo = g_packed[t + PW];
    const unsigned b01hi = g_packed[t + PW + 1];
    const unsigned b10lo = g_packed[t + HB * PW];
    const unsigned b10hi = g_packed[t + HB * PW + 1];
    const unsigned b11lo = g_packed[t + HB * PW + PW];
    const unsigned b11hi = g_packed[t + HB * PW + PW + 1];

    const unsigned mv = interior ? 0xFFFFFFFFu : 0u;   // validity mask
    const unsigned cmlo  = m00lo & mv;
    const unsigned cmhi  = nxt & mv;     // e==31 garbage handled by fixup
    const unsigned a01lo = (b01lo & mv) << 2;
    const unsigned a01hi = __funnelshift_l(b01lo & mv, b01hi & mv, 2);
    const unsigned a10lo = (b10lo & mv) << 4;
    const unsigned a10hi = __funnelshift_l(b10lo & mv, b10hi & mv, 4);
    const unsigned a11lo = (b11lo & mv) << 6;
    const unsigned a11hi = __funnelshift_l(b11lo & mv, b11hi & mv, 6);

    __syncwarp();   // tile is warp-private

    float acc_wbce = 0.f, acc_p = 0.f, acc_pt = 0.f;
    const float acc_t = (float)__popc(m00lo);

    #pragma unroll
    for (int q = 0; q < 8; q++) {
        const float4 xq = s_tile[warp * 256 + swz(lane * 8 + q)];
        #pragma unroll
        for (int pr = 0; pr < 2; pr++) {
            const int e = q * 4 + pr * 2;                 // compile-time
            const float x0 = pr ? xq.z : xq.x;
            const float x1 = pr ? xq.w : xq.y;

            // shared pair extraction
            const unsigned bp  = (m00lo >> e) & 3u;
            const unsigned v00 = __funnelshift_r(cmlo,  cmhi,  e);
            const unsigned v01 = __funnelshift_r(a01lo, a01hi, e);
            const unsigned v10 = __funnelshift_r(a10lo, a10hi, e);
            const unsigned v11 = __funnelshift_r(a11lo, a11hi, e);
            const unsigned c0 = (v00 & 3u) | (v01 & 12u) | (v10 & 48u) | (v11 & 192u);
            const unsigned c1 = ((v00 & 6u) | (v01 & 24u) | (v10 & 96u) | (v11 & 384u)) >> 1;

            // ---- element e ----
            {
                const bool bit = (bp & 1u) != 0u;
                const float z = exp2f(-1.442695041f * x0);
                const float s = 1.f + z;
                float p;
                asm("rcp.approx.f32 %0, %1;" : "=f"(p) : "f"(s));
                const float l2s = __log2f(s);
                const float xnt = bit ? 0.f : x0;
                const float bce = fmaf(0.693147181f, l2s, xnt);
                const float wa1 = s_area2[c0];
                acc_wbce = fmaf(wa1, bce, acc_wbce);
                acc_p += p;
                if (bit) acc_pt += p;
            }
            // ---- element e+1 ----
            {
                const bool bit = (bp & 2u) != 0u;
                const float z = exp2f(-1.442695041f * x1);
                const float s = 1.f + z;
                float p;
                asm("rcp.approx.f32 %0, %1;" : "=f"(p) : "f"(s));
                const float l2s = __log2f(s);
                const float xnt = bit ? 0.f : x1;
                const float bce = fmaf(0.693147181f, l2s, xnt);
                float wa1 = s_area2[c1];
                if (e == 30 && !hiok) wa1 = 1.f;   // w==159 column excluded
                acc_wbce = fmaf(wa1, bce, acc_wbce);
                acc_p += p;
                if (bit) acc_pt += p;
            }
        }
    }

    // ---- block reduction ----
    float v0 = acc_wbce, v1 = acc_p, v2 = acc_pt, v3 = acc_t;
    #pragma unroll
    for (int off = 16; off > 0; off >>= 1) {
        v0 += __shfl_xor_sync(0xffffffffu, v0, off);
        v1 += __shfl_xor_sync(0xffffffffu, v1, off);
        v2 += __shfl_xor_sync(0xffffffffu, v2, off);
        v3 += __shfl_xor_sync(0xffffffffu, v3, off);
    }
    if (lane == 0) { s_red[0][warp] = v0; s_red[1][warp] = v1; s_red[2][warp] = v2; s_red[3][warp] = v3; }
    __syncthreads();
    if (warp == 0) {
        const int nw = TPB / 32;
        v0 = (lane < nw) ? s_red[0][lane] : 0.f;
        v1 = (lane < nw) ? s_red[1][lane] : 0.f;
        v2 = (lane < nw) ? s_red[2][lane] : 0.f;
        v3 = (lane < nw) ? s_red[3][lane] : 0.f;
        #pragma unroll
        for (int off = 4; off > 0; off >>= 1) {
            v0 += __shfl_xor_sync(0xffffffffu, v0, off);
            v1 += __shfl_xor_sync(0xffffffffu, v1, off);
            v2 += __shfl_xor_sync(0xffffffffu, v2, off);
            v3 += __shfl_xor_sync(0xffffffffu, v3, off);
        }
        if (lane == 0) {
            atomicAdd(&g_acc[0], (double)v0);
            atomicAdd(&g_acc[1], (double)v1);
            atomicAdd(&g_acc[2], (double)v2);
            atomicAdd(&g_acc[3], (double)v3);
            __threadfence();
            const unsigned old = atomicAdd(&g_count, 1u);
            if (old == MAIN_BLOCKS - 1) {
                const double a0 = atomicAdd(&g_acc[0], 0.0);
                const double a1 = atomicAdd(&g_acc[1], 0.0);
                const double a2 = atomicAdd(&g_acc[2], 0.0);
                const double a3 = atomicAdd(&g_acc[3], 0.0);
                const double wbce = a0 / (double)NTOT;
                const double dice = 1.0 - (2.0 * a2 + 1.0) / (a1 + a3 + 1.0);
                out[0] = (float)(wbce + dice);
                g_count = 0u;    // g_acc re-zeroed by next pack launch
                __threadfence();
            }
        }
    }
}

extern "C" void kernel_launch(void* const* d_in, const int* in_sizes, int n_in,
                              void* d_out, int out_size) {
    const float* logits     = (const float*)d_in[0];
    const int*   target     = (const int*)d_in[1];
    const float* area_table = (const float*)d_in[2];
    float* out = (float*)d_out;

    pack_kernel<<<PACK_BLOCKS, TPB>>>(target);
    loss_main_kernel<<<MAIN_BLOCKS, TPB>>>(logits, area_table, out);
}